// round 7
// baseline (speedup 1.0000x reference)
#include <cuda_runtime.h>
#include <math.h>

// Problem constants
#define BB 4096
#define KK 64
#define FF 128
#define TE 32
#define DD 160
#define NT 10000
#define INV_SQRT_D 0.07905694150420949f   // 1/sqrt(160)

// ---------------- scratch (__device__ globals; no allocation allowed) ----------
__device__ float g_tbl[NT * TE];     // cos(t*w+b) table, 1.28MB
__device__ float g_M[DD * DD];       // Wk^T Wq / sqrt(D)
__device__ float g_P[DD * DD];       // out_w @ Wv
__device__ float g_m0[DD];           // Wk^T bq / sqrt(D)
__device__ float g_w0[DD];           // Wq^T bk / sqrt(D)
__device__ float g_p0[DD];           // out_w @ bv + out_b
__device__ float g_b00[1];           // bq.bk / sqrt(D)
__device__ float g_U[BB * DD];       // per-target transformed query
__device__ float g_S0[BB];           // per-target score bias
__device__ float g_Acc[BB * DD];     // attn-weighted kv accumulation

// ---------------- kernel 0a: fold weight matrices ------------------------------
// grid 2*DD+1 blocks x DD threads
__global__ void prep_kernel(const float* __restrict__ ipw,
                            const float* __restrict__ ipb,
                            const float* __restrict__ outw,
                            const float* __restrict__ outb) {
    int t = threadIdx.x;
    int bidx = blockIdx.x;
    if (bidx < DD) {
        // M[f,g] = sum_d Wk[d,f] * Wq[d,g] / sqrt(D)   (f = bidx, g = t)
        int f = bidx;
        float acc = 0.f;
        for (int d = 0; d < DD; ++d)
            acc = fmaf(ipw[(DD + d) * DD + f], ipw[d * DD + t], acc);
        g_M[f * DD + t] = acc * INV_SQRT_D;
    } else if (bidx < 2 * DD) {
        // P[e,g] = sum_d out_w[e,d] * Wv[d,g]   (e = bidx-DD, g = t)
        int e = bidx - DD;
        float acc = 0.f;
        for (int d = 0; d < DD; ++d)
            acc = fmaf(outw[e * DD + d], ipw[(2 * DD + d) * DD + t], acc);
        g_P[e * DD + t] = acc;
    } else {
        float m0 = 0.f, w0 = 0.f, p0 = 0.f;
        for (int d = 0; d < DD; ++d) {
            m0 = fmaf(ipw[(DD + d) * DD + t], ipb[d], m0);        // Wk[d,t]*bq[d]
            w0 = fmaf(ipw[d * DD + t], ipb[DD + d], w0);          // Wq[d,t]*bk[d]
            p0 = fmaf(outw[t * DD + d], ipb[2 * DD + d], p0);     // out_w[t,d]*bv[d]
        }
        g_m0[t] = m0 * INV_SQRT_D;
        g_w0[t] = w0 * INV_SQRT_D;
        g_p0[t] = p0 + outb[t];
        if (t == 0) {
            float b00 = 0.f;
            for (int d = 0; d < DD; ++d) b00 = fmaf(ipb[d], ipb[DD + d], b00);
            g_b00[0] = b00 * INV_SQRT_D;
        }
    }
}

// ---------------- kernel 0b: cos table -----------------------------------------
__global__ void tbl_kernel(const float* __restrict__ tw, const float* __restrict__ tb) {
    int idx = blockIdx.x * blockDim.x + threadIdx.x;
    if (idx >= NT * TE) return;
    int t = idx >> 5;
    int j = idx & 31;
    // match reference: f32 multiply then f32 add (no fma contraction), accurate cos
    float arg = __fadd_rn(__fmul_rn((float)t, tw[j]), tb[j]);
    g_tbl[idx] = (float)cos((double)arg);
}

// ---------------- kernel 1: U = M @ q_in + m0, S0 -------------------------------
// grid 128 blocks x 256 thr, each block handles 32 targets, M cached in smem
__global__ void phase1_kernel(const float* __restrict__ x,
                              const int* __restrict__ tgt_ids,
                              const int* __restrict__ tgt_times) {
    extern __shared__ float sh[];
    float* sM   = sh;                   // DD x 161 (padded)
    float* qin  = sM + DD * 161;        // DD
    float* m0s  = qin + DD;             // DD
    float* w0s  = m0s + DD;             // DD
    float* sred = w0s + DD;             // DD
    int t = threadIdx.x;

    for (int i = t; i < DD * DD; i += blockDim.x)
        sM[(i / DD) * 161 + (i % DD)] = g_M[i];
    if (t < DD) { m0s[t] = g_m0[t]; w0s[t] = g_w0[t]; }
    __syncthreads();

    int b0 = blockIdx.x * 32;
    for (int bb = 0; bb < 32; ++bb) {
        int b = b0 + bb;
        int tg = tgt_ids[b];
        int tt = tgt_times[b];
        if (t < FF)       qin[t] = x[tg * FF + t];
        else if (t < DD)  qin[t] = g_tbl[tt * TE + (t - FF)];
        __syncthreads();
        if (t < DD) {
            float acc = m0s[t];
            const float* Mr = &sM[t * 161];
#pragma unroll 8
            for (int g = 0; g < DD; ++g) acc = fmaf(Mr[g], qin[g], acc);
            g_U[b * DD + t] = acc;
            sred[t] = qin[t] * w0s[t];
        }
        __syncthreads();
        if (t < 32) {
            float v = sred[t] + sred[t + 32] + sred[t + 64] + sred[t + 96] + sred[t + 128];
            for (int o = 16; o; o >>= 1) v += __shfl_xor_sync(0xffffffffu, v, o);
            if (t == 0) g_S0[b] = v + g_b00[0];
        }
        __syncthreads();
    }
}

// ---------------- kernel 2: scores, softmax, gumbel/mask, accumulation ----------
// 1 block per target b, 512 threads (16 warps), each warp owns 4 neighbors.
__global__ void __launch_bounds__(512)
phase2_kernel(const float* __restrict__ x,
              const int* __restrict__ nbr_ids,
              const int* __restrict__ etime,
              const float* __restrict__ gum,
              float* __restrict__ out_mask) {
    __shared__ float ssc[KK];
    __shared__ float saw[KK];
    __shared__ float4 part[16][41];   // 16 warps x 40 float4 (padded to 41)

    int b = blockIdx.x;
    int t = threadIdx.x;
    int w = t >> 5;
    int lane = t & 31;
    int kb = w * 4;

    const float4* xv = (const float4*)x;
    const float4* tv = (const float4*)g_tbl;
    const float4* uv = (const float4*)g_U;

    float4 u4 = uv[b * 40 + lane];                       // elements 4*lane..4*lane+3
    float4 ut4 = make_float4(0.f, 0.f, 0.f, 0.f);
    if (lane < 8) ut4 = uv[b * 40 + 32 + lane];          // TE part
    float s0 = g_S0[b];

    int nid[4], et[4];
    float4 xr[4], tr[4];
#pragma unroll
    for (int i = 0; i < 4; ++i) {
        nid[i] = nbr_ids[b * KK + kb + i];
        et[i]  = etime[b * KK + kb + i];
    }
#pragma unroll
    for (int i = 0; i < 4; ++i) xr[i] = xv[nid[i] * 32 + lane];   // coalesced 512B row
#pragma unroll
    for (int i = 0; i < 4; ++i)
        tr[i] = (lane < 8) ? tv[et[i] * 8 + lane] : make_float4(0.f, 0.f, 0.f, 0.f);

#pragma unroll
    for (int i = 0; i < 4; ++i) {
        float p = u4.x * xr[i].x + u4.y * xr[i].y + u4.z * xr[i].z + u4.w * xr[i].w
                + ut4.x * tr[i].x + ut4.y * tr[i].y + ut4.z * tr[i].z + ut4.w * tr[i].w;
        for (int o = 16; o; o >>= 1) p += __shfl_xor_sync(0xffffffffu, p, o);
        if (lane == 0) ssc[kb + i] = p + s0;
    }
    __syncthreads();

    if (w == 0) {
        // softmax over 64 scores: lane handles l and l+32
        float a0 = ssc[lane], a1 = ssc[lane + 32];
        float m = fmaxf(a0, a1);
        for (int o = 16; o; o >>= 1) m = fmaxf(m, __shfl_xor_sync(0xffffffffu, m, o));
        float e0 = expf(a0 - m), e1 = expf(a1 - m);
        float s = e0 + e1;
        for (int o = 16; o; o >>= 1) s += __shfl_xor_sync(0xffffffffu, s, o);
        float aw0 = e0 / s, aw1 = e1 / s;
        saw[lane] = aw0;
        saw[lane + 32] = aw1;
        // gumbel softmax + threshold mask (TAU = 1)
        float gu0 = gum[b * KK + lane], gu1 = gum[b * KK + lane + 32];
        float g0 = -logf(-logf(gu0 + 1e-10f) + 1e-10f);
        float g1 = -logf(-logf(gu1 + 1e-10f) + 1e-10f);
        float z0 = aw0 + g0, z1 = aw1 + g1;
        float zm = fmaxf(z0, z1);
        for (int o = 16; o; o >>= 1) zm = fmaxf(zm, __shfl_xor_sync(0xffffffffu, zm, o));
        float ez0 = expf(z0 - zm), ez1 = expf(z1 - zm);
        float zs = ez0 + ez1;
        for (int o = 16; o; o >>= 1) zs += __shfl_xor_sync(0xffffffffu, zs, o);
        out_mask[b * KK + lane]      = (ez0 / zs > 0.2f) ? 1.0f : 0.0f;
        out_mask[b * KK + lane + 32] = (ez1 / zs > 0.2f) ? 1.0f : 0.0f;
    }
    __syncthreads();

    // accumulate attn_w-weighted kv rows (kv still live in registers)
    float4 ax = make_float4(0.f, 0.f, 0.f, 0.f);
    float4 at = make_float4(0.f, 0.f, 0.f, 0.f);
#pragma unroll
    for (int i = 0; i < 4; ++i) {
        float aw = saw[kb + i];
        ax.x = fmaf(aw, xr[i].x, ax.x);
        ax.y = fmaf(aw, xr[i].y, ax.y);
        ax.z = fmaf(aw, xr[i].z, ax.z);
        ax.w = fmaf(aw, xr[i].w, ax.w);
        at.x = fmaf(aw, tr[i].x, at.x);
        at.y = fmaf(aw, tr[i].y, at.y);
        at.z = fmaf(aw, tr[i].z, at.z);
        at.w = fmaf(aw, tr[i].w, at.w);
    }
    part[w][lane] = ax;
    if (lane < 8) part[w][32 + lane] = at;
    __syncthreads();

    if (t < DD) {
        const float* pf = (const float*)part;   // row stride 41*4 = 164 floats
        float a = 0.f;
#pragma unroll
        for (int ww = 0; ww < 16; ++ww) a += pf[ww * 164 + t];
        g_Acc[b * DD + t] = a;
    }
}

// ---------------- kernel 3: attn_out = P @ acc + p0, mlp + leaky ----------------
// grid 128 blocks x 256 thr, each handles 32 targets, P cached in smem
__global__ void phase3_kernel(const float* __restrict__ ew,
                              const float* __restrict__ mlpw,
                              const float* __restrict__ mlpb,
                              float* __restrict__ out1,
                              float* __restrict__ out2) {
    extern __shared__ float sh[];
    float* sP   = sh;                    // DD x 161
    float* sacc = sP + DD * 161;         // DD
    float* sp0  = sacc + DD;             // DD
    float* smlp = sp0 + DD;              // 161
    float* sred = smlp + 161;            // DD
    float* sdot = sred + DD;             // 2 (dot, mlp_b)
    int t = threadIdx.x;

    for (int i = t; i < DD * DD; i += blockDim.x)
        sP[(i / DD) * 161 + (i % DD)] = g_P[i];
    if (t < DD) sp0[t] = g_p0[t];
    if (t < 161) smlp[t] = mlpw[t];
    if (t == 0) sdot[1] = mlpb[0];
    __syncthreads();

    int b0 = blockIdx.x * 32;
    for (int bb = 0; bb < 32; ++bb) {
        int b = b0 + bb;
        if (t < DD) sacc[t] = g_Acc[b * DD + t];
        __syncthreads();
        if (t < DD) {
            float acc = sp0[t];
            const float* Pr = &sP[t * 161];
#pragma unroll 8
            for (int f = 0; f < DD; ++f) acc = fmaf(Pr[f], sacc[f], acc);
            out1[b * DD + t] = acc;
            sred[t] = acc * smlp[t];
        }
        __syncthreads();
        if (t < 32) {
            float v = sred[t] + sred[t + 32] + sred[t + 64] + sred[t + 96] + sred[t + 128];
            for (int o = 16; o; o >>= 1) v += __shfl_xor_sync(0xffffffffu, v, o);
            if (t == 0) sdot[0] = v;
        }
        __syncthreads();
        if (t < KK) {
            float e = ew[b * KK + t];
            float v = sdot[0] + fmaf(e, smlp[160], sdot[1]);
            out2[b * KK + t] = (v >= 0.f) ? v : 0.01f * v;
        }
        __syncthreads();
    }
}

// ---------------- launch --------------------------------------------------------
extern "C" void kernel_launch(void* const* d_in, const int* in_sizes, int n_in,
                              void* d_out, int out_size) {
    const float* x    = (const float*)d_in[0];
    const int*   tgt  = (const int*)  d_in[1];
    const int*   tt   = (const int*)  d_in[2];
    const int*   nbr  = (const int*)  d_in[3];
    const int*   et   = (const int*)  d_in[4];
    const float* ew   = (const float*)d_in[5];
    const float* gu   = (const float*)d_in[6];
    const float* tew  = (const float*)d_in[7];
    const float* teb  = (const float*)d_in[8];
    const float* ipw  = (const float*)d_in[9];
    const float* ipb  = (const float*)d_in[10];
    const float* outw = (const float*)d_in[11];
    const float* outb = (const float*)d_in[12];
    const float* mlpw = (const float*)d_in[13];
    const float* mlpb = (const float*)d_in[14];

    float* o1 = (float*)d_out;           // attn_output  [B, D]
    float* o2 = o1 + BB * DD;            // new_edge_weight [B, K]
    float* o3 = o2 + BB * KK;            // candidate_mask  [B, K]

    size_t sm1 = (size_t)(DD * 161 + 4 * DD) * sizeof(float);
    size_t sm3 = (size_t)(DD * 161 + DD + DD + 161 + DD + 2) * sizeof(float);
    cudaFuncSetAttribute(phase1_kernel, cudaFuncAttributeMaxDynamicSharedMemorySize, 110 * 1024);
    cudaFuncSetAttribute(phase3_kernel, cudaFuncAttributeMaxDynamicSharedMemorySize, 110 * 1024);

    prep_kernel<<<2 * DD + 1, DD>>>(ipw, ipb, outw, outb);
    tbl_kernel<<<(NT * TE + 255) / 256, 256>>>(tew, teb);
    phase1_kernel<<<128, 256, sm1>>>(x, tgt, tt);
    phase2_kernel<<<BB, 512>>>(x, nbr, et, gu, o3);
    phase3_kernel<<<128, 256, sm3>>>(ew, mlpw, mlpb, o1, o2);
}

// round 8
// speedup vs baseline: 1.0020x; 1.0020x over previous
#include <cuda_runtime.h>
#include <math.h>

// Problem constants
#define BB 4096
#define KK 64
#define FF 128
#define TE 32
#define DD 160
#define NT 10000
#define INV_SQRT_D 0.07905694150420949f   // 1/sqrt(160)

// ---------------- scratch (__device__ globals; no allocation allowed) ----------
__device__ float g_tbl[NT * TE];     // cos(t*w+b) table, 1.28MB
__device__ float g_M[DD * DD];       // Wk^T Wq / sqrt(D)
__device__ float g_P[DD * DD];       // out_w @ Wv
__device__ float g_m0[DD];           // Wk^T bq / sqrt(D)
__device__ float g_w0[DD];           // Wq^T bk / sqrt(D)
__device__ float g_p0[DD];           // out_w @ bv + out_b
__device__ float g_b00[1];           // bq.bk / sqrt(D)
__device__ float g_U[BB * DD];       // per-target transformed query
__device__ float g_S0[BB];           // per-target score bias
__device__ float g_Acc[BB * DD];     // attn-weighted kv accumulation

// ---------------- kernel 0a: fold weight matrices ------------------------------
// grid 2*DD+1 blocks x DD threads
__global__ void prep_kernel(const float* __restrict__ ipw,
                            const float* __restrict__ ipb,
                            const float* __restrict__ outw,
                            const float* __restrict__ outb) {
    int t = threadIdx.x;
    int bidx = blockIdx.x;
    if (bidx < DD) {
        // M[f,g] = sum_d Wk[d,f] * Wq[d,g] / sqrt(D)   (f = bidx, g = t)
        int f = bidx;
        float acc = 0.f;
        for (int d = 0; d < DD; ++d)
            acc = fmaf(ipw[(DD + d) * DD + f], ipw[d * DD + t], acc);
        g_M[f * DD + t] = acc * INV_SQRT_D;
    } else if (bidx < 2 * DD) {
        // P[e,g] = sum_d out_w[e,d] * Wv[d,g]   (e = bidx-DD, g = t)
        int e = bidx - DD;
        float acc = 0.f;
        for (int d = 0; d < DD; ++d)
            acc = fmaf(outw[e * DD + d], ipw[(2 * DD + d) * DD + t], acc);
        g_P[e * DD + t] = acc;
    } else {
        float m0 = 0.f, w0 = 0.f, p0 = 0.f;
        for (int d = 0; d < DD; ++d) {
            m0 = fmaf(ipw[(DD + d) * DD + t], ipb[d], m0);        // Wk[d,t]*bq[d]
            w0 = fmaf(ipw[d * DD + t], ipb[DD + d], w0);          // Wq[d,t]*bk[d]
            p0 = fmaf(outw[t * DD + d], ipb[2 * DD + d], p0);     // out_w[t,d]*bv[d]
        }
        g_m0[t] = m0 * INV_SQRT_D;
        g_w0[t] = w0 * INV_SQRT_D;
        g_p0[t] = p0 + outb[t];
        if (t == 0) {
            float b00 = 0.f;
            for (int d = 0; d < DD; ++d) b00 = fmaf(ipb[d], ipb[DD + d], b00);
            g_b00[0] = b00 * INV_SQRT_D;
        }
    }
}

// ---------------- kernel 0b: cos table -----------------------------------------
__global__ void tbl_kernel(const float* __restrict__ tw, const float* __restrict__ tb) {
    int idx = blockIdx.x * blockDim.x + threadIdx.x;
    if (idx >= NT * TE) return;
    int t = idx >> 5;
    int j = idx & 31;
    // match reference: f32 multiply then f32 add (no fma contraction), accurate cos
    float arg = __fadd_rn(__fmul_rn((float)t, tw[j]), tb[j]);
    g_tbl[idx] = (float)cos((double)arg);
}

// ---------------- kernel 1: U = M @ q_in + m0, S0 -------------------------------
// grid 128 blocks x 256 thr, each block handles 32 targets, M cached in smem
__global__ void phase1_kernel(const float* __restrict__ x,
                              const int* __restrict__ tgt_ids,
                              const int* __restrict__ tgt_times) {
    extern __shared__ float sh[];
    float* sM   = sh;                   // DD x 161 (padded)
    float* qin  = sM + DD * 161;        // DD
    float* m0s  = qin + DD;             // DD
    float* w0s  = m0s + DD;             // DD
    float* sred = w0s + DD;             // DD
    int t = threadIdx.x;

    for (int i = t; i < DD * DD; i += blockDim.x)
        sM[(i / DD) * 161 + (i % DD)] = g_M[i];
    if (t < DD) { m0s[t] = g_m0[t]; w0s[t] = g_w0[t]; }
    __syncthreads();

    int b0 = blockIdx.x * 32;
    for (int bb = 0; bb < 32; ++bb) {
        int b = b0 + bb;
        int tg = tgt_ids[b];
        int tt = tgt_times[b];
        if (t < FF)       qin[t] = x[tg * FF + t];
        else if (t < DD)  qin[t] = g_tbl[tt * TE + (t - FF)];
        __syncthreads();
        if (t < DD) {
            float acc = m0s[t];
            const float* Mr = &sM[t * 161];
#pragma unroll 8
            for (int g = 0; g < DD; ++g) acc = fmaf(Mr[g], qin[g], acc);
            g_U[b * DD + t] = acc;
            sred[t] = qin[t] * w0s[t];
        }
        __syncthreads();
        if (t < 32) {
            float v = sred[t] + sred[t + 32] + sred[t + 64] + sred[t + 96] + sred[t + 128];
            for (int o = 16; o; o >>= 1) v += __shfl_xor_sync(0xffffffffu, v, o);
            if (t == 0) g_S0[b] = v + g_b00[0];
        }
        __syncthreads();
    }
}

// ---------------- kernel 2: scores, softmax, gumbel/mask, accumulation ----------
// 1 block per target b, 512 threads (16 warps), each warp owns 4 neighbors.
__global__ void __launch_bounds__(512)
phase2_kernel(const float* __restrict__ x,
              const int* __restrict__ nbr_ids,
              const int* __restrict__ etime,
              const float* __restrict__ gum,
              float* __restrict__ out_mask) {
    __shared__ float ssc[KK];
    __shared__ float saw[KK];
    __shared__ float4 part[16][41];   // 16 warps x 40 float4 (padded to 41)

    int b = blockIdx.x;
    int t = threadIdx.x;
    int w = t >> 5;
    int lane = t & 31;
    int kb = w * 4;

    const float4* xv = (const float4*)x;
    const float4* tv = (const float4*)g_tbl;
    const float4* uv = (const float4*)g_U;

    float4 u4 = uv[b * 40 + lane];                       // elements 4*lane..4*lane+3
    float4 ut4 = make_float4(0.f, 0.f, 0.f, 0.f);
    if (lane < 8) ut4 = uv[b * 40 + 32 + lane];          // TE part
    float s0 = g_S0[b];

    int nid[4], et[4];
    float4 xr[4], tr[4];
#pragma unroll
    for (int i = 0; i < 4; ++i) {
        nid[i] = nbr_ids[b * KK + kb + i];
        et[i]  = etime[b * KK + kb + i];
    }
#pragma unroll
    for (int i = 0; i < 4; ++i) xr[i] = xv[nid[i] * 32 + lane];   // coalesced 512B row
#pragma unroll
    for (int i = 0; i < 4; ++i)
        tr[i] = (lane < 8) ? tv[et[i] * 8 + lane] : make_float4(0.f, 0.f, 0.f, 0.f);

#pragma unroll
    for (int i = 0; i < 4; ++i) {
        float p = u4.x * xr[i].x + u4.y * xr[i].y + u4.z * xr[i].z + u4.w * xr[i].w
                + ut4.x * tr[i].x + ut4.y * tr[i].y + ut4.z * tr[i].z + ut4.w * tr[i].w;
        for (int o = 16; o; o >>= 1) p += __shfl_xor_sync(0xffffffffu, p, o);
        if (lane == 0) ssc[kb + i] = p + s0;
    }
    __syncthreads();

    if (w == 0) {
        // softmax over 64 scores: lane handles l and l+32
        float a0 = ssc[lane], a1 = ssc[lane + 32];
        float m = fmaxf(a0, a1);
        for (int o = 16; o; o >>= 1) m = fmaxf(m, __shfl_xor_sync(0xffffffffu, m, o));
        float e0 = expf(a0 - m), e1 = expf(a1 - m);
        float s = e0 + e1;
        for (int o = 16; o; o >>= 1) s += __shfl_xor_sync(0xffffffffu, s, o);
        float aw0 = e0 / s, aw1 = e1 / s;
        saw[lane] = aw0;
        saw[lane + 32] = aw1;
        // gumbel softmax + threshold mask (TAU = 1)
        float gu0 = gum[b * KK + lane], gu1 = gum[b * KK + lane + 32];
        float g0 = -logf(-logf(gu0 + 1e-10f) + 1e-10f);
        float g1 = -logf(-logf(gu1 + 1e-10f) + 1e-10f);
        float z0 = aw0 + g0, z1 = aw1 + g1;
        float zm = fmaxf(z0, z1);
        for (int o = 16; o; o >>= 1) zm = fmaxf(zm, __shfl_xor_sync(0xffffffffu, zm, o));
        float ez0 = expf(z0 - zm), ez1 = expf(z1 - zm);
        float zs = ez0 + ez1;
        for (int o = 16; o; o >>= 1) zs += __shfl_xor_sync(0xffffffffu, zs, o);
        out_mask[b * KK + lane]      = (ez0 / zs > 0.2f) ? 1.0f : 0.0f;
        out_mask[b * KK + lane + 32] = (ez1 / zs > 0.2f) ? 1.0f : 0.0f;
    }
    __syncthreads();

    // accumulate attn_w-weighted kv rows (kv still live in registers)
    float4 ax = make_float4(0.f, 0.f, 0.f, 0.f);
    float4 at = make_float4(0.f, 0.f, 0.f, 0.f);
#pragma unroll
    for (int i = 0; i < 4; ++i) {
        float aw = saw[kb + i];
        ax.x = fmaf(aw, xr[i].x, ax.x);
        ax.y = fmaf(aw, xr[i].y, ax.y);
        ax.z = fmaf(aw, xr[i].z, ax.z);
        ax.w = fmaf(aw, xr[i].w, ax.w);
        at.x = fmaf(aw, tr[i].x, at.x);
        at.y = fmaf(aw, tr[i].y, at.y);
        at.z = fmaf(aw, tr[i].z, at.z);
        at.w = fmaf(aw, tr[i].w, at.w);
    }
    part[w][lane] = ax;
    if (lane < 8) part[w][32 + lane] = at;
    __syncthreads();

    if (t < DD) {
        const float* pf = (const float*)part;   // row stride 41*4 = 164 floats
        float a = 0.f;
#pragma unroll
        for (int ww = 0; ww < 16; ++ww) a += pf[ww * 164 + t];
        g_Acc[b * DD + t] = a;
    }
}

// ---------------- kernel 3: attn_out = P @ acc + p0, mlp + leaky ----------------
// grid 128 blocks x 256 thr, each handles 32 targets, P cached in smem
__global__ void phase3_kernel(const float* __restrict__ ew,
                              const float* __restrict__ mlpw,
                              const float* __restrict__ mlpb,
                              float* __restrict__ out1,
                              float* __restrict__ out2) {
    extern __shared__ float sh[];
    float* sP   = sh;                    // DD x 161
    float* sacc = sP + DD * 161;         // DD
    float* sp0  = sacc + DD;             // DD
    float* smlp = sp0 + DD;              // 161
    float* sred = smlp + 161;            // DD
    float* sdot = sred + DD;             // 2 (dot, mlp_b)
    int t = threadIdx.x;

    for (int i = t; i < DD * DD; i += blockDim.x)
        sP[(i / DD) * 161 + (i % DD)] = g_P[i];
    if (t < DD) sp0[t] = g_p0[t];
    if (t < 161) smlp[t] = mlpw[t];
    if (t == 0) sdot[1] = mlpb[0];
    __syncthreads();

    int b0 = blockIdx.x * 32;
    for (int bb = 0; bb < 32; ++bb) {
        int b = b0 + bb;
        if (t < DD) sacc[t] = g_Acc[b * DD + t];
        __syncthreads();
        if (t < DD) {
            float acc = sp0[t];
            const float* Pr = &sP[t * 161];
#pragma unroll 8
            for (int f = 0; f < DD; ++f) acc = fmaf(Pr[f], sacc[f], acc);
            out1[b * DD + t] = acc;
            sred[t] = acc * smlp[t];
        }
        __syncthreads();
        if (t < 32) {
            float v = sred[t] + sred[t + 32] + sred[t + 64] + sred[t + 96] + sred[t + 128];
            for (int o = 16; o; o >>= 1) v += __shfl_xor_sync(0xffffffffu, v, o);
            if (t == 0) sdot[0] = v;
        }
        __syncthreads();
        if (t < KK) {
            float e = ew[b * KK + t];
            float v = sdot[0] + fmaf(e, smlp[160], sdot[1]);
            out2[b * KK + t] = (v >= 0.f) ? v : 0.01f * v;
        }
        __syncthreads();
    }
}

// ---------------- launch --------------------------------------------------------
extern "C" void kernel_launch(void* const* d_in, const int* in_sizes, int n_in,
                              void* d_out, int out_size) {
    const float* x    = (const float*)d_in[0];
    const int*   tgt  = (const int*)  d_in[1];
    const int*   tt   = (const int*)  d_in[2];
    const int*   nbr  = (const int*)  d_in[3];
    const int*   et   = (const int*)  d_in[4];
    const float* ew   = (const float*)d_in[5];
    const float* gu   = (const float*)d_in[6];
    const float* tew  = (const float*)d_in[7];
    const float* teb  = (const float*)d_in[8];
    const float* ipw  = (const float*)d_in[9];
    const float* ipb  = (const float*)d_in[10];
    const float* outw = (const float*)d_in[11];
    const float* outb = (const float*)d_in[12];
    const float* mlpw = (const float*)d_in[13];
    const float* mlpb = (const float*)d_in[14];

    float* o1 = (float*)d_out;           // attn_output  [B, D]
    float* o2 = o1 + BB * DD;            // new_edge_weight [B, K]
    float* o3 = o2 + BB * KK;            // candidate_mask  [B, K]

    size_t sm1 = (size_t)(DD * 161 + 4 * DD) * sizeof(float);
    size_t sm3 = (size_t)(DD * 161 + DD + DD + 161 + DD + 2) * sizeof(float);
    cudaFuncSetAttribute(phase1_kernel, cudaFuncAttributeMaxDynamicSharedMemorySize, 110 * 1024);
    cudaFuncSetAttribute(phase3_kernel, cudaFuncAttributeMaxDynamicSharedMemorySize, 110 * 1024);

    prep_kernel<<<2 * DD + 1, DD>>>(ipw, ipb, outw, outb);
    tbl_kernel<<<(NT * TE + 255) / 256, 256>>>(tew, teb);
    phase1_kernel<<<128, 256, sm1>>>(x, tgt, tt);
    phase2_kernel<<<BB, 512>>>(x, nbr, et, gu, o3);
    phase3_kernel<<<128, 256, sm3>>>(ew, mlpw, mlpb, o1, o2);
}